// round 7
// baseline (speedup 1.0000x reference)
#include <cuda_runtime.h>
#include <cuda_bf16.h>
#include <math.h>

#define NMAX 100000
#define F1   128   // hidden
#define FIN  256

// ---------------- scratch (static __device__ arrays; no allocs allowed) ------
__device__ float g_T1[(size_t)NMAX * F1];   // X @ W1
__device__ float g_H [(size_t)NMAX * F1];   // layer-1 accumulator -> relu'd H (in place)
__device__ float g_AH[(size_t)NMAX * F1];   // agg2 accumulator (A_norm @ H)
__device__ float g_dinv[NMAX];
__device__ int   g_deg [NMAX];

// ---------------- degree ------------------------------------------------------
__global__ void zero_deg_kernel(int* __restrict__ deg, int n) {
    int i = blockIdx.x * blockDim.x + threadIdx.x;
    if (i < n) deg[i] = 0;
}

__global__ void deg_kernel(const int* __restrict__ ei, int E, int Nn, int* __restrict__ deg) {
    int e = blockIdx.x * blockDim.x + threadIdx.x;
    if (e < E) {
        int c = ei[E + e];   // target
        if ((unsigned)c < (unsigned)Nn) atomicAdd(&deg[c], 1);
    }
}

__global__ void dinv_kernel(const int* __restrict__ deg, float* __restrict__ dinv, int n) {
    int i = blockIdx.x * blockDim.x + threadIdx.x;
    if (i < n) dinv[i] = rsqrtf((float)(deg[i] + 1));   // +1 self-loop
}

// ---------------- out[i] = src[i] * dinv[node]^2 (self-loop initializer) ------
__global__ void selfinit_kernel(float* __restrict__ out, const float* __restrict__ src,
                                const float* __restrict__ dinv, int n) {
    int idx = blockIdx.x * blockDim.x + threadIdx.x;   // over n * 32 float4
    if (idx >= n * (F1 / 4)) return;
    int node = idx >> 5;
    float w = dinv[node]; w = w * w;
    float4 s = ((const float4*)src)[idx];
    s.x *= w; s.y *= w; s.z *= w; s.w *= w;
    ((float4*)out)[idx] = s;
}

// ---------------- edge aggregation: out[col] += feat[row] * dinv[r]*dinv[c] ---
// one warp per edge, 128 feats = 32 x float4, scalar REDG.ADD.F32 x4
__global__ void agg_kernel(const int* __restrict__ ei,
                           const float* __restrict__ dinv,
                           const float* __restrict__ feat,
                           float* __restrict__ out, int E, int Nn) {
    int gw   = (blockIdx.x * blockDim.x + threadIdx.x) >> 5;
    int lane = threadIdx.x & 31;
    if (gw >= E) return;
    int r = ei[gw];
    int c = ei[E + gw];
    if ((unsigned)r >= (unsigned)Nn || (unsigned)c >= (unsigned)Nn) return;
    float w = __ldg(&dinv[r]) * __ldg(&dinv[c]);
    float4 v = ((const float4*)(feat + (size_t)r * F1))[lane];
    float* dst = out + (size_t)c * F1 + lane * 4;
    atomicAdd(dst + 0, v.x * w);
    atomicAdd(dst + 1, v.y * w);
    atomicAdd(dst + 2, v.z * w);
    atomicAdd(dst + 3, v.w * w);
}

// ---------------- H = relu(H + b1) (self-loop already folded in) --------------
__global__ void relu_bias_kernel(float* __restrict__ H, const float* __restrict__ b1, int n) {
    int idx = blockIdx.x * blockDim.x + threadIdx.x;   // over n * 32 float4
    if (idx >= n * (F1 / 4)) return;
    int f4 = idx & 31;
    float4 a = ((const float4*)H)[idx];
    float4 b = ((const float4*)b1)[f4];
    a.x = fmaxf(a.x + b.x, 0.f);
    a.y = fmaxf(a.y + b.y, 0.f);
    a.z = fmaxf(a.z + b.z, 0.f);
    a.w = fmaxf(a.w + b.w, 0.f);
    ((float4*)H)[idx] = a;
}

// ---------------- tiled fp32 GEMM: C[M,N] = A[M,K] @ B[K,N] (+bias) -----------
template<int BM, int BN, int BK, int TM, int TN, bool BIAS>
__global__ void sgemm_kernel(const float* __restrict__ A, const float* __restrict__ B,
                             const float* __restrict__ bias, float* __restrict__ C,
                             int M, int N, int K) {
    constexpr int THREADS = (BM / TM) * (BN / TN);
    __shared__ float As[BK][BM + 4];
    __shared__ float Bs[BK][BN];
    const int tid  = threadIdx.x;
    const int brow = blockIdx.y * BM;
    const int bcol = blockIdx.x * BN;
    const int tr = (tid / (BN / TN)) * TM;
    const int tc = (tid % (BN / TN)) * TN;
    float acc[TM][TN] = {};

    constexpr int A_F4 = BM * BK / 4;
    constexpr int B_F4 = BK * BN / 4;

    for (int k0 = 0; k0 < K; k0 += BK) {
        #pragma unroll
        for (int i = tid; i < A_F4; i += THREADS) {
            int r  = i / (BK / 4);
            int kq = i % (BK / 4);
            float4 v = make_float4(0.f, 0.f, 0.f, 0.f);
            int gr = brow + r;
            if (gr < M) v = *(const float4*)(A + (size_t)gr * K + k0 + kq * 4);
            As[kq * 4 + 0][r] = v.x;
            As[kq * 4 + 1][r] = v.y;
            As[kq * 4 + 2][r] = v.z;
            As[kq * 4 + 3][r] = v.w;
        }
        #pragma unroll
        for (int i = tid; i < B_F4; i += THREADS) {
            int kk = i / (BN / 4);
            int c4 = i % (BN / 4);
            *(float4*)&Bs[kk][c4 * 4] =
                *(const float4*)(B + (size_t)(k0 + kk) * N + bcol + c4 * 4);
        }
        __syncthreads();
        #pragma unroll
        for (int kk = 0; kk < BK; kk++) {
            float ra[TM], rb[TN];
            #pragma unroll
            for (int i = 0; i < TM; i++) ra[i] = As[kk][tr + i];
            #pragma unroll
            for (int j = 0; j < TN; j++) rb[j] = Bs[kk][tc + j];
            #pragma unroll
            for (int i = 0; i < TM; i++)
                #pragma unroll
                for (int j = 0; j < TN; j++)
                    acc[i][j] = fmaf(ra[i], rb[j], acc[i][j]);
        }
        __syncthreads();
    }

    #pragma unroll
    for (int i = 0; i < TM; i++) {
        int gr = brow + tr + i;
        if (gr >= M) continue;
        #pragma unroll
        for (int j = 0; j < TN; j += 4) {
            float4 v;
            v.x = acc[i][j + 0]; v.y = acc[i][j + 1];
            v.z = acc[i][j + 2]; v.w = acc[i][j + 3];
            if (BIAS) {
                int col = bcol + tc + j;
                v.x += bias[col + 0]; v.y += bias[col + 1];
                v.z += bias[col + 2]; v.w += bias[col + 3];
            }
            *(float4*)(C + (size_t)gr * N + bcol + tc + j) = v;
        }
    }
}

// ---------------- launch ------------------------------------------------------
extern "C" void kernel_launch(void* const* d_in, const int* in_sizes, int n_in,
                              void* d_out, int out_size) {
    const float* X   = (const float*)d_in[0];
    const int*   ei  = (const int*)d_in[1];        // edge_index as int32 (JAX x64-off)
    const float* W1  = (const float*)d_in[2];
    const float* b1  = (const float*)d_in[3];
    const float* Wmu = (const float*)d_in[4];
    const float* bmu = (const float*)d_in[5];
    const float* Wlv = (const float*)d_in[6];
    const float* blv = (const float*)d_in[7];
    const int Nn = in_sizes[0] / FIN;       // 100000
    const int E  = in_sizes[1] / 2;         // 1600000
    float* out = (float*)d_out;

    float *T1, *H, *AH, *dinv; int* deg;
    cudaGetSymbolAddress((void**)&T1,   g_T1);
    cudaGetSymbolAddress((void**)&H,    g_H);
    cudaGetSymbolAddress((void**)&AH,   g_AH);
    cudaGetSymbolAddress((void**)&dinv, g_dinv);
    cudaGetSymbolAddress((void**)&deg,  g_deg);

    const int n4 = Nn * (F1 / 4);

    // degrees + dinv (no memset nodes; explicit zero kernel)
    zero_deg_kernel<<<(Nn + 255) / 256, 256>>>(deg, Nn);
    deg_kernel<<<(E + 255) / 256, 256>>>(ei, E, Nn, deg);
    dinv_kernel<<<(Nn + 255) / 256, 256>>>(deg, dinv, Nn);

    // T1 = X @ W1   [100000,256]x[256,128]
    {
        dim3 grid(F1 / 128, (Nn + 127) / 128);
        sgemm_kernel<128, 128, 32, 8, 8, false><<<grid, 256>>>(X, W1, nullptr, T1, Nn, F1, FIN);
    }

    // layer 1: H = T1*dinv^2 (self-loop init), += edges, then bias+relu
    {
        selfinit_kernel<<<(n4 + 255) / 256, 256>>>(H, T1, dinv, Nn);
        int warps_per_block = 8;
        int blocks = (E + warps_per_block - 1) / warps_per_block;
        agg_kernel<<<blocks, warps_per_block * 32>>>(ei, dinv, T1, H, E, Nn);
        relu_bias_kernel<<<(n4 + 255) / 256, 256>>>(H, b1, Nn);
    }

    // layer-2 aggregation (shared by mu and lv): AH = A_norm @ H
    {
        selfinit_kernel<<<(n4 + 255) / 256, 256>>>(AH, H, dinv, Nn);
        int warps_per_block = 8;
        int blocks = (E + warps_per_block - 1) / warps_per_block;
        agg_kernel<<<blocks, warps_per_block * 32>>>(ei, dinv, H, AH, E, Nn);
    }

    // mu = AH @ Wmu + bmu ; lv = AH @ Wlv + blv   [100000,128]x[128,64]
    {
        dim3 grid(1, (Nn + 127) / 128);
        sgemm_kernel<128, 64, 32, 8, 4, true><<<grid, 256>>>(AH, Wmu, bmu, out, Nn, 64, F1);
        sgemm_kernel<128, 64, 32, 8, 4, true><<<grid, 256>>>(AH, Wlv, blv, out + (size_t)Nn * 64, Nn, 64, F1);
    }
}

// round 8
// speedup vs baseline: 1.5065x; 1.5065x over previous
#include <cuda_runtime.h>
#include <cuda_bf16.h>
#include <math.h>

#define NMAX 100000
#define F1   128   // hidden
#define FIN  256

// ---------------- scratch (static __device__ arrays; no allocs allowed) ------
__device__ float g_T1[(size_t)NMAX * F1];   // X @ W1
__device__ float g_H [(size_t)NMAX * F1];   // layer-1 accumulator -> relu'd H (in place)
__device__ float g_AH[(size_t)NMAX * F1];   // agg2 accumulator (A_norm @ H)
__device__ float g_dinv[NMAX];
__device__ int   g_deg [NMAX];

// ---------------- degree ------------------------------------------------------
__global__ void zero_deg_kernel(int* __restrict__ deg, int n) {
    int i = blockIdx.x * blockDim.x + threadIdx.x;
    if (i < n) deg[i] = 0;
}

__global__ void deg_kernel(const int* __restrict__ ei, int E, int Nn, int* __restrict__ deg) {
    int e = blockIdx.x * blockDim.x + threadIdx.x;
    if (e < E) {
        int c = ei[E + e];   // target
        if ((unsigned)c < (unsigned)Nn) atomicAdd(&deg[c], 1);
    }
}

__global__ void dinv_kernel(const int* __restrict__ deg, float* __restrict__ dinv, int n) {
    int i = blockIdx.x * blockDim.x + threadIdx.x;
    if (i < n) dinv[i] = rsqrtf((float)(deg[i] + 1));   // +1 self-loop
}

// ---------------- out[i] = src[i] * dinv[node]^2 (self-loop initializer) ------
__global__ void selfinit_kernel(float* __restrict__ out, const float* __restrict__ src,
                                const float* __restrict__ dinv, int n) {
    int idx = blockIdx.x * blockDim.x + threadIdx.x;   // over n * 32 float4
    if (idx >= n * (F1 / 4)) return;
    int node = idx >> 5;
    float w = dinv[node]; w = w * w;
    float4 s = ((const float4*)src)[idx];
    s.x *= w; s.y *= w; s.z *= w; s.w *= w;
    ((float4*)out)[idx] = s;
}

// ---------------- edge aggregation: out[col] += feat[row] * dinv[r]*dinv[c] ---
// one warp per edge, 128 feats = 32 x float4, ONE red.global.add.v4.f32 per lane
__global__ void agg_kernel(const int* __restrict__ ei,
                           const float* __restrict__ dinv,
                           const float* __restrict__ feat,
                           float* __restrict__ out, int E, int Nn) {
    int gw   = (blockIdx.x * blockDim.x + threadIdx.x) >> 5;
    int lane = threadIdx.x & 31;
    if (gw >= E) return;
    int r = ei[gw];
    int c = ei[E + gw];
    if ((unsigned)r >= (unsigned)Nn || (unsigned)c >= (unsigned)Nn) return;
    float w = __ldg(&dinv[r]) * __ldg(&dinv[c]);
    float4 v = ((const float4*)(feat + (size_t)r * F1))[lane];
    v.x *= w; v.y *= w; v.z *= w; v.w *= w;
    float* dst = out + (size_t)c * F1 + lane * 4;   // 16B aligned
    asm volatile("red.global.add.v4.f32 [%0], {%1, %2, %3, %4};"
                 :: "l"(dst), "f"(v.x), "f"(v.y), "f"(v.z), "f"(v.w) : "memory");
}

// ---------------- H = relu(H + b1) (self-loop already folded in) --------------
__global__ void relu_bias_kernel(float* __restrict__ H, const float* __restrict__ b1, int n) {
    int idx = blockIdx.x * blockDim.x + threadIdx.x;   // over n * 32 float4
    if (idx >= n * (F1 / 4)) return;
    int f4 = idx & 31;
    float4 a = ((const float4*)H)[idx];
    float4 b = ((const float4*)b1)[f4];
    a.x = fmaxf(a.x + b.x, 0.f);
    a.y = fmaxf(a.y + b.y, 0.f);
    a.z = fmaxf(a.z + b.z, 0.f);
    a.w = fmaxf(a.w + b.w, 0.f);
    ((float4*)H)[idx] = a;
}

// ---------------- tiled fp32 GEMM: C[M,N] = A[M,K] @ B[K,N] -------------------
template<int BM, int BN, int BK, int TM, int TN>
__global__ void sgemm_kernel(const float* __restrict__ A, const float* __restrict__ B,
                             float* __restrict__ C, int M, int N, int K) {
    constexpr int THREADS = (BM / TM) * (BN / TN);
    __shared__ float As[BK][BM + 4];
    __shared__ float Bs[BK][BN];
    const int tid  = threadIdx.x;
    const int brow = blockIdx.y * BM;
    const int bcol = blockIdx.x * BN;
    const int tr = (tid / (BN / TN)) * TM;
    const int tc = (tid % (BN / TN)) * TN;
    float acc[TM][TN] = {};

    constexpr int A_F4 = BM * BK / 4;
    constexpr int B_F4 = BK * BN / 4;

    for (int k0 = 0; k0 < K; k0 += BK) {
        #pragma unroll
        for (int i = tid; i < A_F4; i += THREADS) {
            int r  = i / (BK / 4);
            int kq = i % (BK / 4);
            float4 v = make_float4(0.f, 0.f, 0.f, 0.f);
            int gr = brow + r;
            if (gr < M) v = *(const float4*)(A + (size_t)gr * K + k0 + kq * 4);
            As[kq * 4 + 0][r] = v.x;
            As[kq * 4 + 1][r] = v.y;
            As[kq * 4 + 2][r] = v.z;
            As[kq * 4 + 3][r] = v.w;
        }
        #pragma unroll
        for (int i = tid; i < B_F4; i += THREADS) {
            int kk = i / (BN / 4);
            int c4 = i % (BN / 4);
            *(float4*)&Bs[kk][c4 * 4] =
                *(const float4*)(B + (size_t)(k0 + kk) * N + bcol + c4 * 4);
        }
        __syncthreads();
        #pragma unroll
        for (int kk = 0; kk < BK; kk++) {
            float ra[TM], rb[TN];
            #pragma unroll
            for (int i = 0; i < TM; i++) ra[i] = As[kk][tr + i];
            #pragma unroll
            for (int j = 0; j < TN; j++) rb[j] = Bs[kk][tc + j];
            #pragma unroll
            for (int i = 0; i < TM; i++)
                #pragma unroll
                for (int j = 0; j < TN; j++)
                    acc[i][j] = fmaf(ra[i], rb[j], acc[i][j]);
        }
        __syncthreads();
    }

    #pragma unroll
    for (int i = 0; i < TM; i++) {
        int gr = brow + tr + i;
        if (gr >= M) continue;
        #pragma unroll
        for (int j = 0; j < TN; j += 4) {
            float4 v;
            v.x = acc[i][j + 0]; v.y = acc[i][j + 1];
            v.z = acc[i][j + 2]; v.w = acc[i][j + 3];
            *(float4*)(C + (size_t)gr * N + bcol + tc + j) = v;
        }
    }
}

// --------- fused tail GEMM: [mu | lv] = AH @ [Wmu | Wlv] + [bmu | blv] --------
// BM=128 rows, BN=128 cols (cols 0..63 -> mu, 64..127 -> lv), K=128.
// Reads AH once for both heads; writes to split output regions.
template<int BM, int BK, int TM, int TN>
__global__ void tail_gemm_kernel(const float* __restrict__ A,
                                 const float* __restrict__ Wmu, const float* __restrict__ bmu,
                                 const float* __restrict__ Wlv, const float* __restrict__ blv,
                                 float* __restrict__ out, int M, int K) {
    constexpr int BN = 128;
    constexpr int THREADS = (BM / TM) * (BN / TN);
    __shared__ float As[BK][BM + 4];
    __shared__ float Bs[BK][BN];
    const int tid  = threadIdx.x;
    const int brow = blockIdx.y * BM;
    const int tr = (tid / (BN / TN)) * TM;
    const int tc = (tid % (BN / TN)) * TN;
    float acc[TM][TN] = {};

    constexpr int A_F4 = BM * BK / 4;
    constexpr int B_F4 = BK * BN / 4;

    for (int k0 = 0; k0 < K; k0 += BK) {
        #pragma unroll
        for (int i = tid; i < A_F4; i += THREADS) {
            int r  = i / (BK / 4);
            int kq = i % (BK / 4);
            float4 v = make_float4(0.f, 0.f, 0.f, 0.f);
            int gr = brow + r;
            if (gr < M) v = *(const float4*)(A + (size_t)gr * K + k0 + kq * 4);
            As[kq * 4 + 0][r] = v.x;
            As[kq * 4 + 1][r] = v.y;
            As[kq * 4 + 2][r] = v.z;
            As[kq * 4 + 3][r] = v.w;
        }
        // B: cols 0..63 from Wmu, 64..127 from Wlv (each [K,64])
        #pragma unroll
        for (int i = tid; i < B_F4; i += THREADS) {
            int kk = i / (BN / 4);
            int c4 = i % (BN / 4);          // 0..31; c4<16 -> mu, else lv
            const float* src = (c4 < 16) ? (Wmu + (size_t)(k0 + kk) * 64 + c4 * 4)
                                         : (Wlv + (size_t)(k0 + kk) * 64 + (c4 - 16) * 4);
            *(float4*)&Bs[kk][c4 * 4] = *(const float4*)src;
        }
        __syncthreads();
        #pragma unroll
        for (int kk = 0; kk < BK; kk++) {
            float ra[TM], rb[TN];
            #pragma unroll
            for (int i = 0; i < TM; i++) ra[i] = As[kk][tr + i];
            #pragma unroll
            for (int j = 0; j < TN; j++) rb[j] = Bs[kk][tc + j];
            #pragma unroll
            for (int i = 0; i < TM; i++)
                #pragma unroll
                for (int j = 0; j < TN; j++)
                    acc[i][j] = fmaf(ra[i], rb[j], acc[i][j]);
        }
        __syncthreads();
    }

    #pragma unroll
    for (int i = 0; i < TM; i++) {
        int gr = brow + tr + i;
        if (gr >= M) continue;
        #pragma unroll
        for (int j = 0; j < TN; j += 4) {
            int col = tc + j;               // 0..127
            int lcol = (col < 64) ? col : col - 64;
            const float* bias = (col < 64) ? bmu : blv;
            float* base = (col < 64) ? out : out + (size_t)M * 64;
            float4 v;
            v.x = acc[i][j + 0] + bias[lcol + 0];
            v.y = acc[i][j + 1] + bias[lcol + 1];
            v.z = acc[i][j + 2] + bias[lcol + 2];
            v.w = acc[i][j + 3] + bias[lcol + 3];
            *(float4*)(base + (size_t)gr * 64 + lcol) = v;
        }
    }
}

// ---------------- launch ------------------------------------------------------
extern "C" void kernel_launch(void* const* d_in, const int* in_sizes, int n_in,
                              void* d_out, int out_size) {
    const float* X   = (const float*)d_in[0];
    const int*   ei  = (const int*)d_in[1];        // edge_index as int32 (JAX x64-off)
    const float* W1  = (const float*)d_in[2];
    const float* b1  = (const float*)d_in[3];
    const float* Wmu = (const float*)d_in[4];
    const float* bmu = (const float*)d_in[5];
    const float* Wlv = (const float*)d_in[6];
    const float* blv = (const float*)d_in[7];
    const int Nn = in_sizes[0] / FIN;       // 100000
    const int E  = in_sizes[1] / 2;         // 1600000
    float* out = (float*)d_out;

    float *T1, *H, *AH, *dinv; int* deg;
    cudaGetSymbolAddress((void**)&T1,   g_T1);
    cudaGetSymbolAddress((void**)&H,    g_H);
    cudaGetSymbolAddress((void**)&AH,   g_AH);
    cudaGetSymbolAddress((void**)&dinv, g_dinv);
    cudaGetSymbolAddress((void**)&deg,  g_deg);

    const int n4 = Nn * (F1 / 4);

    // degrees + dinv
    zero_deg_kernel<<<(Nn + 255) / 256, 256>>>(deg, Nn);
    deg_kernel<<<(E + 255) / 256, 256>>>(ei, E, Nn, deg);
    dinv_kernel<<<(Nn + 255) / 256, 256>>>(deg, dinv, Nn);

    // T1 = X @ W1   [100000,256]x[256,128]
    {
        dim3 grid(1, (Nn + 127) / 128);
        sgemm_kernel<128, 128, 32, 8, 8><<<grid, 256>>>(X, W1, T1, Nn, F1, FIN);
    }

    // layer 1: H = T1*dinv^2 (self-loop init), += edges, then bias+relu
    {
        selfinit_kernel<<<(n4 + 255) / 256, 256>>>(H, T1, dinv, Nn);
        int warps_per_block = 8;
        int blocks = (E + warps_per_block - 1) / warps_per_block;
        agg_kernel<<<blocks, warps_per_block * 32>>>(ei, dinv, T1, H, E, Nn);
        relu_bias_kernel<<<(n4 + 255) / 256, 256>>>(H, b1, Nn);
    }

    // layer-2 aggregation (shared by mu and lv): AH = A_norm @ H
    {
        selfinit_kernel<<<(n4 + 255) / 256, 256>>>(AH, H, dinv, Nn);
        int warps_per_block = 8;
        int blocks = (E + warps_per_block - 1) / warps_per_block;
        agg_kernel<<<blocks, warps_per_block * 32>>>(ei, dinv, H, AH, E, Nn);
    }

    // [mu | lv] = AH @ [Wmu | Wlv] + bias   (single fused kernel, AH read once)
    {
        dim3 grid(1, (Nn + 127) / 128);
        tail_gemm_kernel<128, 32, 8, 8><<<grid, 256>>>(AH, Wmu, bmu, Wlv, blv, out, Nn, F1);
    }
}

// round 9
// speedup vs baseline: 2.5207x; 1.6732x over previous
#include <cuda_runtime.h>
#include <cuda_bf16.h>
#include <math.h>

#define NMAX 100000
#define EMAX 1600000
#define F1   128   // hidden
#define FIN  256

// ---------------- scratch (static __device__ arrays) --------------------------
__device__ float g_T1[(size_t)NMAX * F1];   // T1s = (X@W1)*dinv[row]; later Hs
__device__ float g_H [(size_t)NMAX * F1];   // agg1 raw out; later agg2 raw out
__device__ float g_AH[(size_t)NMAX * F1];   // Hs = relu(...)*dinv
__device__ float g_dinv[NMAX];
__device__ int   g_deg [NMAX];
__device__ int   g_rowstart[NMAX];
__device__ int   g_cur[NMAX];
__device__ int   g_csr[EMAX];
__device__ int   g_blocksums[512];
__device__ int   g_blockoff[512];

// ---------------- degree ------------------------------------------------------
__global__ void zero_deg_kernel(int* __restrict__ deg, int n) {
    int i = blockIdx.x * blockDim.x + threadIdx.x;
    if (i < n) deg[i] = 0;
}

__global__ void deg_kernel(const int* __restrict__ ei, int E, int Nn, int* __restrict__ deg) {
    int e = blockIdx.x * blockDim.x + threadIdx.x;
    if (e < E) {
        int c = ei[E + e];   // target
        if ((unsigned)c < (unsigned)Nn) atomicAdd(&deg[c], 1);
    }
}

__global__ void dinv_kernel(const int* __restrict__ deg, float* __restrict__ dinv, int n) {
    int i = blockIdx.x * blockDim.x + threadIdx.x;
    if (i < n) dinv[i] = rsqrtf((float)(deg[i] + 1));   // +1 self-loop
}

// ---------------- prefix-sum (3 kernels) for CSR row starts -------------------
__global__ void scan1_kernel(const int* __restrict__ deg, int n,
                             int* __restrict__ row_start, int* __restrict__ blockSums) {
    __shared__ int s[256];
    int tid = threadIdx.x;
    int i = blockIdx.x * 256 + tid;
    int v = (i < n) ? deg[i] : 0;
    s[tid] = v; __syncthreads();
    #pragma unroll
    for (int off = 1; off < 256; off <<= 1) {
        int t = (tid >= off) ? s[tid - off] : 0;
        __syncthreads();
        s[tid] += t;
        __syncthreads();
    }
    if (i < n) row_start[i] = s[tid] - v;      // exclusive
    if (tid == 255) blockSums[blockIdx.x] = s[255];
}

__global__ void scan2_kernel(const int* __restrict__ blockSums, int nb,
                             int* __restrict__ blockOff) {
    __shared__ int s[512];
    int tid = threadIdx.x;
    int v = (tid < nb) ? blockSums[tid] : 0;
    s[tid] = v; __syncthreads();
    #pragma unroll
    for (int off = 1; off < 512; off <<= 1) {
        int t = (tid >= off) ? s[tid - off] : 0;
        __syncthreads();
        s[tid] += t;
        __syncthreads();
    }
    if (tid < nb) blockOff[tid] = s[tid] - v;  // exclusive
}

__global__ void scan3_kernel(int* __restrict__ row_start, const int* __restrict__ blockOff,
                             int n, int* __restrict__ cur) {
    int i = blockIdx.x * blockDim.x + threadIdx.x;
    if (i < n) {
        int rs = row_start[i] + blockOff[blockIdx.x * blockDim.x / 256 + (threadIdx.x >= 256 ? 1 : 0)];
        // NOTE: blockDim must be 256 so block index maps 1:1 to scan1 blocks
        row_start[i] = rs;
        cur[i] = rs;
    }
}

__global__ void fill_kernel(const int* __restrict__ ei, int E, int Nn,
                            int* __restrict__ cur, int* __restrict__ csr) {
    int e = blockIdx.x * blockDim.x + threadIdx.x;
    if (e < E) {
        int r = ei[e];
        int c = ei[E + e];
        if ((unsigned)r < (unsigned)Nn && (unsigned)c < (unsigned)Nn) {
            int pos = atomicAdd(&cur[c], 1);
            csr[pos] = r;
        }
    }
}

// ---------------- CSR gather aggregation: out[c] = feat[c] + sum_nbr feat[r] --
// one warp per node, lane = one float4 of the 128-feature row
__global__ void agg_csr_kernel(const int* __restrict__ row_start,
                               const int* __restrict__ deg,
                               const int* __restrict__ csr,
                               const float* __restrict__ feat,
                               float* __restrict__ out, int Nn) {
    int node = (blockIdx.x * blockDim.x + threadIdx.x) >> 5;
    int lane = threadIdx.x & 31;
    if (node >= Nn) return;
    int start = row_start[node];
    int len   = deg[node];
    const float4* f4 = (const float4*)feat;
    float4 acc = f4[(size_t)node * 32 + lane];      // self term (pre-scaled feat)
    int j = 0;
    for (; j + 4 <= len; j += 4) {
        int r0 = __ldg(csr + start + j + 0);
        int r1 = __ldg(csr + start + j + 1);
        int r2 = __ldg(csr + start + j + 2);
        int r3 = __ldg(csr + start + j + 3);
        float4 a = f4[(size_t)r0 * 32 + lane];
        float4 b = f4[(size_t)r1 * 32 + lane];
        float4 c = f4[(size_t)r2 * 32 + lane];
        float4 d = f4[(size_t)r3 * 32 + lane];
        acc.x += (a.x + b.x) + (c.x + d.x);
        acc.y += (a.y + b.y) + (c.y + d.y);
        acc.z += (a.z + b.z) + (c.z + d.z);
        acc.w += (a.w + b.w) + (c.w + d.w);
    }
    for (; j < len; j++) {
        int r = __ldg(csr + start + j);
        float4 a = f4[(size_t)r * 32 + lane];
        acc.x += a.x; acc.y += a.y; acc.z += a.z; acc.w += a.w;
    }
    ((float4*)out)[(size_t)node * 32 + lane] = acc;
}

// ------- Hs = relu(Hraw * dinv[node] + b1) * dinv[node] -----------------------
__global__ void relu_scale_kernel(const float* __restrict__ Hraw, float* __restrict__ Hs,
                                  const float* __restrict__ dinv,
                                  const float* __restrict__ b1, int n) {
    int idx = blockIdx.x * blockDim.x + threadIdx.x;   // over n * 32 float4
    if (idx >= n * (F1 / 4)) return;
    int node = idx >> 5;
    int f4   = idx & 31;
    float w = dinv[node];
    float4 a = ((const float4*)Hraw)[idx];
    float4 b = ((const float4*)b1)[f4];
    float4 o;
    o.x = fmaxf(fmaf(a.x, w, b.x), 0.f) * w;
    o.y = fmaxf(fmaf(a.y, w, b.y), 0.f) * w;
    o.z = fmaxf(fmaf(a.z, w, b.z), 0.f) * w;
    o.w = fmaxf(fmaf(a.w, w, b.w), 0.f) * w;
    ((float4*)Hs)[idx] = o;
}

// ---------------- tiled fp32 GEMM: C[M,N] = (A[M,K] @ B[K,N]) * rowscale[m] ---
template<int BM, int BN, int BK, int TM, int TN>
__global__ void sgemm_oscale_kernel(const float* __restrict__ A, const float* __restrict__ B,
                                    const float* __restrict__ rowscale,
                                    float* __restrict__ C, int M, int N, int K) {
    constexpr int THREADS = (BM / TM) * (BN / TN);
    __shared__ float As[BK][BM + 4];
    __shared__ float Bs[BK][BN];
    const int tid  = threadIdx.x;
    const int brow = blockIdx.y * BM;
    const int bcol = blockIdx.x * BN;
    const int tr = (tid / (BN / TN)) * TM;
    const int tc = (tid % (BN / TN)) * TN;
    float acc[TM][TN] = {};

    constexpr int A_F4 = BM * BK / 4;
    constexpr int B_F4 = BK * BN / 4;

    for (int k0 = 0; k0 < K; k0 += BK) {
        #pragma unroll
        for (int i = tid; i < A_F4; i += THREADS) {
            int r  = i / (BK / 4);
            int kq = i % (BK / 4);
            float4 v = make_float4(0.f, 0.f, 0.f, 0.f);
            int gr = brow + r;
            if (gr < M) v = *(const float4*)(A + (size_t)gr * K + k0 + kq * 4);
            As[kq * 4 + 0][r] = v.x;
            As[kq * 4 + 1][r] = v.y;
            As[kq * 4 + 2][r] = v.z;
            As[kq * 4 + 3][r] = v.w;
        }
        #pragma unroll
        for (int i = tid; i < B_F4; i += THREADS) {
            int kk = i / (BN / 4);
            int c4 = i % (BN / 4);
            *(float4*)&Bs[kk][c4 * 4] =
                *(const float4*)(B + (size_t)(k0 + kk) * N + bcol + c4 * 4);
        }
        __syncthreads();
        #pragma unroll
        for (int kk = 0; kk < BK; kk++) {
            float ra[TM], rb[TN];
            #pragma unroll
            for (int i = 0; i < TM; i++) ra[i] = As[kk][tr + i];
            #pragma unroll
            for (int j = 0; j < TN; j++) rb[j] = Bs[kk][tc + j];
            #pragma unroll
            for (int i = 0; i < TM; i++)
                #pragma unroll
                for (int j = 0; j < TN; j++)
                    acc[i][j] = fmaf(ra[i], rb[j], acc[i][j]);
        }
        __syncthreads();
    }

    #pragma unroll
    for (int i = 0; i < TM; i++) {
        int gr = brow + tr + i;
        if (gr >= M) continue;
        float w = rowscale[gr];
        #pragma unroll
        for (int j = 0; j < TN; j += 4) {
            float4 v;
            v.x = acc[i][j + 0] * w; v.y = acc[i][j + 1] * w;
            v.z = acc[i][j + 2] * w; v.w = acc[i][j + 3] * w;
            *(float4*)(C + (size_t)gr * N + bcol + tc + j) = v;
        }
    }
}

// --------- fused tail GEMM: [mu | lv] = (A*rowscale) @ [Wmu | Wlv] + bias -----
template<int BM, int BK, int TM, int TN>
__global__ void tail_gemm_kernel(const float* __restrict__ A,
                                 const float* __restrict__ rowscale,
                                 const float* __restrict__ Wmu, const float* __restrict__ bmu,
                                 const float* __restrict__ Wlv, const float* __restrict__ blv,
                                 float* __restrict__ out, int M, int K) {
    constexpr int BN = 128;
    constexpr int THREADS = (BM / TM) * (BN / TN);
    __shared__ float As[BK][BM + 4];
    __shared__ float Bs[BK][BN];
    const int tid  = threadIdx.x;
    const int brow = blockIdx.y * BM;
    const int tr = (tid / (BN / TN)) * TM;
    const int tc = (tid % (BN / TN)) * TN;
    float acc[TM][TN] = {};

    constexpr int A_F4 = BM * BK / 4;
    constexpr int B_F4 = BK * BN / 4;

    for (int k0 = 0; k0 < K; k0 += BK) {
        #pragma unroll
        for (int i = tid; i < A_F4; i += THREADS) {
            int r  = i / (BK / 4);
            int kq = i % (BK / 4);
            float4 v = make_float4(0.f, 0.f, 0.f, 0.f);
            int gr = brow + r;
            if (gr < M) {
                v = *(const float4*)(A + (size_t)gr * K + k0 + kq * 4);
                float w = rowscale[gr];
                v.x *= w; v.y *= w; v.z *= w; v.w *= w;
            }
            As[kq * 4 + 0][r] = v.x;
            As[kq * 4 + 1][r] = v.y;
            As[kq * 4 + 2][r] = v.z;
            As[kq * 4 + 3][r] = v.w;
        }
        #pragma unroll
        for (int i = tid; i < B_F4; i += THREADS) {
            int kk = i / (BN / 4);
            int c4 = i % (BN / 4);          // 0..31; c4<16 -> mu, else lv
            const float* src = (c4 < 16) ? (Wmu + (size_t)(k0 + kk) * 64 + c4 * 4)
                                         : (Wlv + (size_t)(k0 + kk) * 64 + (c4 - 16) * 4);
            *(float4*)&Bs[kk][c4 * 4] = *(const float4*)src;
        }
        __syncthreads();
        #pragma unroll
        for (int kk = 0; kk < BK; kk++) {
            float ra[TM], rb[TN];
            #pragma unroll
            for (int i = 0; i < TM; i++) ra[i] = As[kk][tr + i];
            #pragma unroll
            for (int j = 0; j < TN; j++) rb[j] = Bs[kk][tc + j];
            #pragma unroll
            for (int i = 0; i < TM; i++)
                #pragma unroll
                for (int j = 0; j < TN; j++)
                    acc[i][j] = fmaf(ra[i], rb[j], acc[i][j]);
        }
        __syncthreads();
    }

    #pragma unroll
    for (int i = 0; i < TM; i++) {
        int gr = brow + tr + i;
        if (gr >= M) continue;
        #pragma unroll
        for (int j = 0; j < TN; j += 4) {
            int col = tc + j;               // 0..127
            int lcol = (col < 64) ? col : col - 64;
            const float* bias = (col < 64) ? bmu : blv;
            float* base = (col < 64) ? out : out + (size_t)M * 64;
            float4 v;
            v.x = acc[i][j + 0] + bias[lcol + 0];
            v.y = acc[i][j + 1] + bias[lcol + 1];
            v.z = acc[i][j + 2] + bias[lcol + 2];
            v.w = acc[i][j + 3] + bias[lcol + 3];
            *(float4*)(base + (size_t)gr * 64 + lcol) = v;
        }
    }
}

// ---------------- launch ------------------------------------------------------
extern "C" void kernel_launch(void* const* d_in, const int* in_sizes, int n_in,
                              void* d_out, int out_size) {
    const float* X   = (const float*)d_in[0];
    const int*   ei  = (const int*)d_in[1];        // edge_index as int32 (JAX x64-off)
    const float* W1  = (const float*)d_in[2];
    const float* b1  = (const float*)d_in[3];
    const float* Wmu = (const float*)d_in[4];
    const float* bmu = (const float*)d_in[5];
    const float* Wlv = (const float*)d_in[6];
    const float* blv = (const float*)d_in[7];
    const int Nn = in_sizes[0] / FIN;       // 100000
    const int E  = in_sizes[1] / 2;         // 1600000
    float* out = (float*)d_out;

    float *T1, *H, *AH, *dinv;
    int *deg, *row_start, *cur, *csr, *bsums, *boff;
    cudaGetSymbolAddress((void**)&T1,       g_T1);
    cudaGetSymbolAddress((void**)&H,        g_H);
    cudaGetSymbolAddress((void**)&AH,       g_AH);
    cudaGetSymbolAddress((void**)&dinv,     g_dinv);
    cudaGetSymbolAddress((void**)&deg,      g_deg);
    cudaGetSymbolAddress((void**)&row_start,g_rowstart);
    cudaGetSymbolAddress((void**)&cur,      g_cur);
    cudaGetSymbolAddress((void**)&csr,      g_csr);
    cudaGetSymbolAddress((void**)&bsums,    g_blocksums);
    cudaGetSymbolAddress((void**)&boff,     g_blockoff);

    const int n4 = Nn * (F1 / 4);
    const int nblk256 = (Nn + 255) / 256;   // 391

    // degrees + dinv
    zero_deg_kernel<<<nblk256, 256>>>(deg, Nn);
    deg_kernel<<<(E + 255) / 256, 256>>>(ei, E, Nn, deg);
    dinv_kernel<<<nblk256, 256>>>(deg, dinv, Nn);

    // CSR build: row_start = exclusive-scan(deg); fill csr with sources per target
    scan1_kernel<<<nblk256, 256>>>(deg, Nn, row_start, bsums);
    scan2_kernel<<<1, 512>>>(bsums, nblk256, boff);
    scan3_kernel<<<nblk256, 256>>>(row_start, boff, Nn, cur);
    fill_kernel<<<(E + 255) / 256, 256>>>(ei, E, Nn, cur, csr);

    // T1s = (X @ W1) * dinv[row]
    {
        dim3 grid(1, (Nn + 127) / 128);
        sgemm_oscale_kernel<128, 128, 32, 8, 8><<<grid, 256>>>(X, W1, dinv, T1, Nn, F1, FIN);
    }

    // layer 1 aggregation (gather): Hraw[c] = T1s[c] + sum_r T1s[r]
    {
        int threads = 256;                              // 8 warps/block
        int blocks = (Nn * 32 + threads - 1) / threads; // one warp per node
        agg_csr_kernel<<<blocks, threads>>>(row_start, deg, csr, T1, H, Nn);
    }

    // Hs = relu(Hraw * dinv + b1) * dinv
    relu_scale_kernel<<<(n4 + 255) / 256, 256>>>(H, AH, dinv, b1, Nn);

    // layer 2 aggregation (gather): AHraw[c] = Hs[c] + sum_r Hs[r]  -> into H
    {
        int threads = 256;
        int blocks = (Nn * 32 + threads - 1) / threads;
        agg_csr_kernel<<<blocks, threads>>>(row_start, deg, csr, AH, H, Nn);
    }

    // [mu | lv] = (AHraw * dinv[row]) @ [Wmu | Wlv] + bias
    {
        dim3 grid(1, (Nn + 127) / 128);
        tail_gemm_kernel<128, 32, 8, 8><<<grid, 256>>>(H, dinv, Wmu, bmu, Wlv, blv, out, Nn, F1);
    }
}